// round 2
// baseline (speedup 1.0000x reference)
#include <cuda_runtime.h>

// TemporalTransformerBlock: N=65536 independent sequences, T=24, D=16, 4 heads,
// dff=64, 2 post-norm encoder layers. One warp per sequence, lane t = token t.
// All d_model-dim matmuls are thread-local (hidden vector lives in registers);
// attention couples tokens via a per-warp smem K/V tile read with broadcast
// LDS.128 + online softmax. Weights staged once per CTA into smem.

#define NSEQ   65536
#define SEQ_T  24
#define DM     16
#define NH     4
#define HDIM   4
#define DFF_   64
#define NL     2
#define WPC    4                      // warps (sequences) per CTA
#define CTA_THREADS (WPC * 32)

__device__ __forceinline__ float dot16(const float* h, const float* w) {
    const float4* w4 = reinterpret_cast<const float4*>(w);
    float s = 0.f;
#pragma unroll
    for (int i = 0; i < 4; i++) {
        float4 ww = w4[i];
        s = fmaf(h[4*i+0], ww.x, s);
        s = fmaf(h[4*i+1], ww.y, s);
        s = fmaf(h[4*i+2], ww.z, s);
        s = fmaf(h[4*i+3], ww.w, s);
    }
    return s;
}

__device__ __forceinline__ void lnorm16(float* h, const float* w, const float* b) {
    float mu = 0.f;
#pragma unroll
    for (int d = 0; d < DM; d++) mu += h[d];
    mu *= (1.0f / DM);
    float var = 0.f;
#pragma unroll
    for (int d = 0; d < DM; d++) { float c = h[d] - mu; var = fmaf(c, c, var); }
    var *= (1.0f / DM);
    float inv = rsqrtf(var + 1e-5f);
#pragma unroll
    for (int d = 0; d < DM; d++) h[d] = (h[d] - mu) * inv * w[d] + b[d];
}

__global__ void __launch_bounds__(CTA_THREADS)
tt_kernel(const float* __restrict__ gx,
          const float* __restrict__ gWin,  const float* __restrict__ gbin,
          const float* __restrict__ gWqkv, const float* __restrict__ gbqkv,
          const float* __restrict__ gWo,   const float* __restrict__ gbo,
          const float* __restrict__ gln1w, const float* __restrict__ gln1b,
          const float* __restrict__ gW1,   const float* __restrict__ gb1,
          const float* __restrict__ gW2,   const float* __restrict__ gb2,
          const float* __restrict__ gln2w, const float* __restrict__ gln2b,
          const float* __restrict__ gWout, const float* __restrict__ gbout,
          float* __restrict__ gout)
{
    __shared__ __align__(16) float sWqkv[NL][3*DM][DM];
    __shared__ float sbqkv[NL][3*DM];
    __shared__ __align__(16) float sWo[NL][DM][DM];
    __shared__ float sbo[NL][DM];
    __shared__ float sln1w[NL][DM], sln1b[NL][DM];
    __shared__ __align__(16) float sW1[NL][DFF_][DM];
    __shared__ float sb1[NL][DFF_];
    __shared__ __align__(16) float sW2T[NL][DFF_][DM];   // transposed: [j][d]
    __shared__ float sb2[NL][DM];
    __shared__ float sln2w[NL][DM], sln2b[NL][DM];
    __shared__ __align__(16) float sWin[DM], sbin[DM], sWout[DM];
    __shared__ float sbout;
    __shared__ __align__(16) float skv[WPC][2][SEQ_T][DM];   // per-warp K/V tile

    const int tid = threadIdx.x;

    // ---- stage weights into smem ----
    for (int i = tid; i < NL*3*DM*DM; i += CTA_THREADS) (&sWqkv[0][0][0])[i] = gWqkv[i];
    for (int i = tid; i < NL*3*DM;    i += CTA_THREADS) (&sbqkv[0][0])[i]    = gbqkv[i];
    for (int i = tid; i < NL*DM*DM;   i += CTA_THREADS) (&sWo[0][0][0])[i]   = gWo[i];
    for (int i = tid; i < NL*DM;      i += CTA_THREADS) {
        (&sbo[0][0])[i]   = gbo[i];
        (&sln1w[0][0])[i] = gln1w[i];
        (&sln1b[0][0])[i] = gln1b[i];
        (&sb2[0][0])[i]   = gb2[i];
        (&sln2w[0][0])[i] = gln2w[i];
        (&sln2b[0][0])[i] = gln2b[i];
    }
    for (int i = tid; i < NL*DFF_*DM; i += CTA_THREADS) (&sW1[0][0][0])[i] = gW1[i];
    for (int i = tid; i < NL*DFF_;    i += CTA_THREADS) (&sb1[0][0])[i]    = gb1[i];
    for (int i = tid; i < NL*DFF_*DM; i += CTA_THREADS) {
        int l = i / (DFF_*DM), r = i % (DFF_*DM);
        int j = r / DM, d = r % DM;
        sW2T[l][j][d] = gW2[l*DM*DFF_ + d*DFF_ + j];     // W2 is [L, D, DFF]
    }
    if (tid < DM) {
        sWin[tid]  = gWin[tid];
        sbin[tid]  = gbin[tid];
        sWout[tid] = gWout[tid];
    }
    if (tid == 0) sbout = gbout[0];
    __syncthreads();

    const int warp = tid >> 5, lane = tid & 31;
    const int n = blockIdx.x * WPC + warp;               // sequence id
    const int t = (lane < SEQ_T) ? lane : (SEQ_T - 1);   // token id (clamped)
    const bool active = (lane < SEQ_T);

    float (*kvk)[DM] = skv[warp][0];
    float (*kvv)[DM] = skv[warp][1];

    // ---- input projection: h = x_t * Win + bin (rank-1) ----
    float h[DM];
    {
        float xv = gx[t * NSEQ + n];
#pragma unroll
        for (int d = 0; d < DM; d++) h[d] = fmaf(xv, sWin[d], sbin[d]);
    }

#pragma unroll 1
    for (int l = 0; l < NL; l++) {
        // ---- QKV projection (thread-local over d_model) ----
        float q[DM];
#pragma unroll
        for (int j = 0; j < DM; j++) q[j] = dot16(h, sWqkv[l][j]) + sbqkv[l][j];
        {
            float kk[DM], vv[DM];
#pragma unroll
            for (int j = 0; j < DM; j++) kk[j] = dot16(h, sWqkv[l][DM + j])   + sbqkv[l][DM + j];
#pragma unroll
            for (int j = 0; j < DM; j++) vv[j] = dot16(h, sWqkv[l][2*DM + j]) + sbqkv[l][2*DM + j];
            __syncwarp();   // previous layer's attention reads must be done
            if (active) {
                float4* kd = (float4*)kvk[t];
                float4* vd = (float4*)kvv[t];
#pragma unroll
                for (int i = 0; i < 4; i++) {
                    kd[i] = make_float4(kk[4*i], kk[4*i+1], kk[4*i+2], kk[4*i+3]);
                    vd[i] = make_float4(vv[4*i], vv[4*i+1], vv[4*i+2], vv[4*i+3]);
                }
            }
            __syncwarp();
        }

        // ---- attention: online softmax over s, K/V via smem broadcast ----
        float m[NH], lsum[NH], ctx[DM];
#pragma unroll
        for (int hh = 0; hh < NH; hh++) { m[hh] = -1e30f; lsum[hh] = 0.f; }
#pragma unroll
        for (int d = 0; d < DM; d++) ctx[d] = 0.f;

#pragma unroll 2
        for (int s = 0; s < SEQ_T; s++) {
            float ks[DM], vs[DM];
            const float4* kp = (const float4*)kvk[s];
            const float4* vp = (const float4*)kvv[s];
#pragma unroll
            for (int i = 0; i < 4; i++) {
                float4 a = kp[i]; ks[4*i]=a.x; ks[4*i+1]=a.y; ks[4*i+2]=a.z; ks[4*i+3]=a.w;
                float4 b = vp[i]; vs[4*i]=b.x; vs[4*i+1]=b.y; vs[4*i+2]=b.z; vs[4*i+3]=b.w;
            }
#pragma unroll
            for (int hh = 0; hh < NH; hh++) {
                float logit = 0.f;
#pragma unroll
                for (int e = 0; e < HDIM; e++)
                    logit = fmaf(q[hh*HDIM+e], ks[hh*HDIM+e], logit);
                logit *= 0.5f;                           // 1/sqrt(head_dim)
                float mn   = fmaxf(m[hh], logit);
                float corr = __expf(m[hh] - mn);
                float p    = __expf(logit - mn);
                lsum[hh] = fmaf(lsum[hh], corr, p);
                m[hh] = mn;
#pragma unroll
                for (int e = 0; e < HDIM; e++)
                    ctx[hh*HDIM+e] = fmaf(ctx[hh*HDIM+e], corr, p * vs[hh*HDIM+e]);
            }
        }
#pragma unroll
        for (int hh = 0; hh < NH; hh++) {
            float inv = 1.0f / lsum[hh];
#pragma unroll
            for (int e = 0; e < HDIM; e++) ctx[hh*HDIM+e] *= inv;
        }

        // ---- output proj + residual + LN1 ----
#pragma unroll
        for (int d = 0; d < DM; d++) h[d] += dot16(ctx, sWo[l][d]) + sbo[l][d];
        lnorm16(h, sln1w[l], sln1b[l]);

        // ---- feed-forward (64 hidden, fused accumulate) + residual + LN2 ----
        float acc[DM];
#pragma unroll
        for (int d = 0; d < DM; d++) acc[d] = sb2[l][d];
#pragma unroll 4
        for (int j = 0; j < DFF_; j++) {
            float a = dot16(h, sW1[l][j]) + sb1[l][j];
            a = fmaxf(a, 0.f);
            const float4* w2 = (const float4*)sW2T[l][j];
#pragma unroll
            for (int i = 0; i < 4; i++) {
                float4 ww = w2[i];
                acc[4*i+0] = fmaf(a, ww.x, acc[4*i+0]);
                acc[4*i+1] = fmaf(a, ww.y, acc[4*i+1]);
                acc[4*i+2] = fmaf(a, ww.z, acc[4*i+2]);
                acc[4*i+3] = fmaf(a, ww.w, acc[4*i+3]);
            }
        }
#pragma unroll
        for (int d = 0; d < DM; d++) h[d] += acc[d];
        lnorm16(h, sln2w[l], sln2b[l]);
    }

    // ---- output projection ----
    float y = dot16(h, sWout) + sbout;
    if (active) gout[t * NSEQ + n] = y;
}

extern "C" void kernel_launch(void* const* d_in, const int* in_sizes, int n_in,
                              void* d_out, int out_size)
{
    (void)in_sizes; (void)n_in; (void)out_size;
    const float* gx    = (const float*)d_in[0];
    const float* gWin  = (const float*)d_in[1];
    const float* gbin  = (const float*)d_in[2];
    const float* gWqkv = (const float*)d_in[3];
    const float* gbqkv = (const float*)d_in[4];
    const float* gWo   = (const float*)d_in[5];
    const float* gbo   = (const float*)d_in[6];
    const float* gln1w = (const float*)d_in[7];
    const float* gln1b = (const float*)d_in[8];
    const float* gW1   = (const float*)d_in[9];
    const float* gb1   = (const float*)d_in[10];
    const float* gW2   = (const float*)d_in[11];
    const float* gb2   = (const float*)d_in[12];
    const float* gln2w = (const float*)d_in[13];
    const float* gln2b = (const float*)d_in[14];
    const float* gWout = (const float*)d_in[15];
    const float* gbout = (const float*)d_in[16];
    float* gout = (float*)d_out;

    tt_kernel<<<NSEQ / WPC, CTA_THREADS>>>(
        gx, gWin, gbin, gWqkv, gbqkv, gWo, gbo, gln1w, gln1b,
        gW1, gb1, gW2, gb2, gln2w, gln2b, gWout, gbout, gout);
}

// round 3
// speedup vs baseline: 1.4893x; 1.4893x over previous
#include <cuda_runtime.h>

// TemporalTransformerBlock on GB300: N=65536 independent T=24 sequences,
// D=16, 4 heads, dff=64, 2 post-norm layers.
// R3: pack TWO sequences per lane in f32x2 (component = sequence).
//  - weight smem loads amortize over 2 tokens (LSU was 86.9%)
//  - fma.rn.f32x2 halves FMA-pipe instr (fma pipe was saturated at 52.4%)
//  - weight dup (w,w) via mov.b64 lands on the idle ALU pipe (was 10.6%)
//  - softmax without running-max (logits are ~0.1; exp2-safe), halving MUFU
// One warp = one sequence PAIR, lane t = token t. K/V in smem as [d][t] ull
// so stores are conflict-free and reads grab (s,s+1) as LDS.128 broadcast.

#define NSEQ   65536
#define SEQ_T  24
#define DM     16
#define NH     4
#define HDIM   4
#define DFF_   64
#define NL     2
#define WPC    4
#define CTA_THREADS (WPC * 32)

typedef unsigned long long f2;   // packed (seqA, seqB) fp32 pair

__device__ __forceinline__ f2 pk(float x, float y) {
    f2 r; asm("mov.b64 %0, {%1, %2};" : "=l"(r) : "f"(x), "f"(y)); return r;
}
__device__ __forceinline__ f2 dupf(float x) {
    f2 r; asm("mov.b64 %0, {%1, %1};" : "=l"(r) : "f"(x)); return r;
}
__device__ __forceinline__ void upk(f2 v, float& x, float& y) {
    asm("mov.b64 {%0, %1}, %2;" : "=f"(x), "=f"(y) : "l"(v));
}
__device__ __forceinline__ f2 fma2(f2 a, f2 b, f2 c) {
    f2 d; asm("fma.rn.f32x2 %0, %1, %2, %3;" : "=l"(d) : "l"(a), "l"(b), "l"(c)); return d;
}
__device__ __forceinline__ f2 add2(f2 a, f2 b) {
    f2 d; asm("add.rn.f32x2 %0, %1, %2;" : "=l"(d) : "l"(a), "l"(b)); return d;
}
__device__ __forceinline__ f2 mul2(f2 a, f2 b) {
    f2 d; asm("mul.rn.f32x2 %0, %1, %2;" : "=l"(d) : "l"(a), "l"(b)); return d;
}
__device__ __forceinline__ float ex2(float x) {
    float r; asm("ex2.approx.f32 %0, %1;" : "=f"(r) : "f"(x)); return r;
}
__device__ __forceinline__ float rcpf(float x) {
    float r; asm("rcp.approx.f32 %0, %1;" : "=f"(r) : "f"(x)); return r;
}

struct Smem {
    float Wqkv[NL][3*DM][DM];
    float bqkv[NL][3*DM];
    float Wo[NL][DM][DM];
    float bo[NL][DM];
    float ln1w[NL][DM], ln1b[NL][DM];
    float W1[NL][DFF_][DM];
    float b1[NL][DFF_];
    float W2T[NL][DFF_][DM];     // [j][d]
    float b2[NL][DM];
    float ln2w[NL][DM], ln2b[NL][DM];
    float Win[DM], bin_[DM], Wout[DM];
    float bout_;
    float pad_;
    __align__(16) f2 kv[WPC][2][DM][SEQ_T];   // [k/v][d][t], 16B-aligned rows
};

// dot over 16 dims: packed hidden x scalar weights (dup'd), 2 partial chains
__device__ __forceinline__ f2 dot16(const f2* h, const float* w, f2 init) {
    const float4* w4 = reinterpret_cast<const float4*>(w);
    float4 a = w4[0], b = w4[1], c = w4[2], d = w4[3];
    f2 s0 = fma2(h[0],  dupf(a.x), init);
    f2 s1 = mul2(h[1],  dupf(a.y));
    s0 = fma2(h[2],  dupf(a.z), s0);
    s1 = fma2(h[3],  dupf(a.w), s1);
    s0 = fma2(h[4],  dupf(b.x), s0);
    s1 = fma2(h[5],  dupf(b.y), s1);
    s0 = fma2(h[6],  dupf(b.z), s0);
    s1 = fma2(h[7],  dupf(b.w), s1);
    s0 = fma2(h[8],  dupf(c.x), s0);
    s1 = fma2(h[9],  dupf(c.y), s1);
    s0 = fma2(h[10], dupf(c.z), s0);
    s1 = fma2(h[11], dupf(c.w), s1);
    s0 = fma2(h[12], dupf(d.x), s0);
    s1 = fma2(h[13], dupf(d.y), s1);
    s0 = fma2(h[14], dupf(d.z), s0);
    s1 = fma2(h[15], dupf(d.w), s1);
    return add2(s0, s1);
}

__device__ __forceinline__ void lnorm2(f2* h, const float* w, const float* b) {
    f2 s0 = add2(h[0], h[1]), s1 = add2(h[2], h[3]);
    f2 s2 = add2(h[4], h[5]), s3 = add2(h[6], h[7]);
#pragma unroll
    for (int i = 0; i < 2; i++) {
        s0 = add2(s0, add2(h[8+4*i],  h[9+4*i]));
        s1 = add2(s1, add2(h[10+4*i], h[11+4*i]));
    }
    f2 sum = add2(add2(s0, s1), add2(s2, s3));
    f2 nmu = mul2(sum, dupf(-1.0f / DM));
    f2 v0 = 0ull, v1 = 0ull;
#pragma unroll
    for (int d = 0; d < DM; d += 2) {
        f2 c0 = add2(h[d],   nmu);
        f2 c1 = add2(h[d+1], nmu);
        v0 = fma2(c0, c0, v0);
        v1 = fma2(c1, c1, v1);
    }
    f2 var = add2(v0, v1);
    float va, vb; upk(var, va, vb);
    va = rsqrtf(va * (1.0f / DM) + 1e-5f);
    vb = rsqrtf(vb * (1.0f / DM) + 1e-5f);
    f2 inv = pk(va, vb);
#pragma unroll
    for (int d = 0; d < DM; d++) {
        f2 c = add2(h[d], nmu);
        h[d] = fma2(mul2(c, inv), dupf(w[d]), dupf(b[d]));
    }
}

__global__ void __launch_bounds__(CTA_THREADS, 3)
tt_kernel(const float* __restrict__ gx,
          const float* __restrict__ gWin,  const float* __restrict__ gbin,
          const float* __restrict__ gWqkv, const float* __restrict__ gbqkv,
          const float* __restrict__ gWo,   const float* __restrict__ gbo,
          const float* __restrict__ gln1w, const float* __restrict__ gln1b,
          const float* __restrict__ gW1,   const float* __restrict__ gb1,
          const float* __restrict__ gW2,   const float* __restrict__ gb2,
          const float* __restrict__ gln2w, const float* __restrict__ gln2b,
          const float* __restrict__ gWout, const float* __restrict__ gbout,
          float* __restrict__ gout)
{
    extern __shared__ char smem_raw[];
    Smem& S = *reinterpret_cast<Smem*>(smem_raw);

    const int tid = threadIdx.x;

    // ---- stage weights ----
    for (int i = tid; i < NL*3*DM*DM; i += CTA_THREADS) (&S.Wqkv[0][0][0])[i] = gWqkv[i];
    for (int i = tid; i < NL*3*DM;    i += CTA_THREADS) (&S.bqkv[0][0])[i]    = gbqkv[i];
    for (int i = tid; i < NL*DM*DM;   i += CTA_THREADS) (&S.Wo[0][0][0])[i]   = gWo[i];
    for (int i = tid; i < NL*DM;      i += CTA_THREADS) {
        (&S.bo[0][0])[i]   = gbo[i];
        (&S.ln1w[0][0])[i] = gln1w[i];
        (&S.ln1b[0][0])[i] = gln1b[i];
        (&S.b2[0][0])[i]   = gb2[i];
        (&S.ln2w[0][0])[i] = gln2w[i];
        (&S.ln2b[0][0])[i] = gln2b[i];
    }
    for (int i = tid; i < NL*DFF_*DM; i += CTA_THREADS) (&S.W1[0][0][0])[i] = gW1[i];
    for (int i = tid; i < NL*DFF_;    i += CTA_THREADS) (&S.b1[0][0])[i]    = gb1[i];
    for (int i = tid; i < NL*DFF_*DM; i += CTA_THREADS) {
        int l = i / (DFF_*DM), r = i % (DFF_*DM);
        int j = r / DM, d = r % DM;
        S.W2T[l][j][d] = gW2[l*DM*DFF_ + d*DFF_ + j];
    }
    if (tid < DM) {
        S.Win[tid]  = gWin[tid];
        S.bin_[tid] = gbin[tid];
        S.Wout[tid] = gWout[tid];
    }
    if (tid == 0) S.bout_ = gbout[0];
    __syncthreads();

    const int warp = tid >> 5, lane = tid & 31;
    const int pair = blockIdx.x * WPC + warp;            // sequence pair id
    const int n0 = 2 * pair;                              // even -> float2 aligned
    const int t = (lane < SEQ_T) ? lane : (SEQ_T - 1);
    const bool active = (lane < SEQ_T);

    f2* KK = &S.kv[warp][0][0][0];   // [16][24]
    f2* VV = &S.kv[warp][1][0][0];

    // ---- input projection (rank-1), both sequences at once ----
    f2 h[DM];
    {
        float2 xv = *reinterpret_cast<const float2*>(gx + (size_t)t * NSEQ + n0);
        f2 xp = pk(xv.x, xv.y);
#pragma unroll
        for (int d = 0; d < DM; d++)
            h[d] = fma2(xp, dupf(S.Win[d]), dupf(S.bin_[d]));
    }

#pragma unroll 1
    for (int l = 0; l < NL; l++) {
        // ---- K, V projections -> smem (layout [d][t]) ----
        __syncwarp();
#pragma unroll 4
        for (int j = 0; j < DM; j++) {
            f2 kkv = dot16(h, S.Wqkv[l][DM + j], dupf(S.bqkv[l][DM + j]));
            if (active) KK[j * SEQ_T + t] = kkv;
        }
#pragma unroll 4
        for (int j = 0; j < DM; j++) {
            f2 vvv = dot16(h, S.Wqkv[l][2*DM + j], dupf(S.bqkv[l][2*DM + j]));
            if (active) VV[j * SEQ_T + t] = vvv;
        }
        // ---- Q projection, pre-scaled by (1/sqrt(hd)) * log2(e) ----
        f2 q[DM];
        {
            const f2 qs = dupf(0.5f * 1.4426950408889634f);
#pragma unroll 4
            for (int j = 0; j < DM; j++)
                q[j] = mul2(dot16(h, S.Wqkv[l][j], dupf(S.bqkv[l][j])), qs);
        }
        __syncwarp();

        // ---- attention: plain-softmax (logits tiny), s unrolled by 2 ----
        f2 lsum[NH], ctx[DM];
#pragma unroll
        for (int hh = 0; hh < NH; hh++) lsum[hh] = 0ull;
#pragma unroll
        for (int d = 0; d < DM; d++) ctx[d] = 0ull;

#pragma unroll 2
        for (int s2 = 0; s2 < SEQ_T / 2; s2++) {
            const int s = 2 * s2;
#pragma unroll
            for (int hh = 0; hh < NH; hh++) {
                const int d0 = hh * HDIM;
                ulonglong2 k0 = *reinterpret_cast<const ulonglong2*>(&KK[(d0+0)*SEQ_T + s]);
                ulonglong2 k1 = *reinterpret_cast<const ulonglong2*>(&KK[(d0+1)*SEQ_T + s]);
                ulonglong2 k2 = *reinterpret_cast<const ulonglong2*>(&KK[(d0+2)*SEQ_T + s]);
                ulonglong2 k3 = *reinterpret_cast<const ulonglong2*>(&KK[(d0+3)*SEQ_T + s]);
                f2 la = mul2(q[d0+0], k0.x);
                f2 lb = mul2(q[d0+0], k0.y);
                la = fma2(q[d0+1], k1.x, la);
                lb = fma2(q[d0+1], k1.y, lb);
                la = fma2(q[d0+2], k2.x, la);
                lb = fma2(q[d0+2], k2.y, lb);
                la = fma2(q[d0+3], k3.x, la);
                lb = fma2(q[d0+3], k3.y, lb);
                float laA, laB, lbA, lbB;
                upk(la, laA, laB); upk(lb, lbA, lbB);
                f2 pa = pk(ex2(laA), ex2(laB));
                f2 pb = pk(ex2(lbA), ex2(lbB));
                lsum[hh] = add2(lsum[hh], add2(pa, pb));
                ulonglong2 v0 = *reinterpret_cast<const ulonglong2*>(&VV[(d0+0)*SEQ_T + s]);
                ulonglong2 v1 = *reinterpret_cast<const ulonglong2*>(&VV[(d0+1)*SEQ_T + s]);
                ulonglong2 v2 = *reinterpret_cast<const ulonglong2*>(&VV[(d0+2)*SEQ_T + s]);
                ulonglong2 v3 = *reinterpret_cast<const ulonglong2*>(&VV[(d0+3)*SEQ_T + s]);
                ctx[d0+0] = fma2(pa, v0.x, ctx[d0+0]);
                ctx[d0+1] = fma2(pa, v1.x, ctx[d0+1]);
                ctx[d0+2] = fma2(pa, v2.x, ctx[d0+2]);
                ctx[d0+3] = fma2(pa, v3.x, ctx[d0+3]);
                ctx[d0+0] = fma2(pb, v0.y, ctx[d0+0]);
                ctx[d0+1] = fma2(pb, v1.y, ctx[d0+1]);
                ctx[d0+2] = fma2(pb, v2.y, ctx[d0+2]);
                ctx[d0+3] = fma2(pb, v3.y, ctx[d0+3]);
            }
        }
#pragma unroll
        for (int hh = 0; hh < NH; hh++) {
            float sa, sb; upk(lsum[hh], sa, sb);
            f2 inv = pk(rcpf(sa), rcpf(sb));
#pragma unroll
            for (int e = 0; e < HDIM; e++)
                ctx[hh*HDIM + e] = mul2(ctx[hh*HDIM + e], inv);
        }

        // ---- output proj + residual + LN1 ----
#pragma unroll 4
        for (int d = 0; d < DM; d++)
            h[d] = add2(h[d], dot16(ctx, S.Wo[l][d], dupf(S.bo[l][d])));
        lnorm2(h, S.ln1w[l], S.ln1b[l]);

        // ---- FFN + residual + LN2 ----
        f2 acc[DM];
#pragma unroll
        for (int d = 0; d < DM; d++) acc[d] = dupf(S.b2[l][d]);
#pragma unroll 4
        for (int j = 0; j < DFF_; j++) {
            f2 a = dot16(h, S.W1[l][j], dupf(S.b1[l][j]));
            float aa, ab; upk(a, aa, ab);
            a = pk(fmaxf(aa, 0.f), fmaxf(ab, 0.f));
            const float4* w2 = reinterpret_cast<const float4*>(S.W2T[l][j]);
            float4 wa = w2[0], wb = w2[1], wc = w2[2], wd = w2[3];
            acc[0]  = fma2(a, dupf(wa.x), acc[0]);
            acc[1]  = fma2(a, dupf(wa.y), acc[1]);
            acc[2]  = fma2(a, dupf(wa.z), acc[2]);
            acc[3]  = fma2(a, dupf(wa.w), acc[3]);
            acc[4]  = fma2(a, dupf(wb.x), acc[4]);
            acc[5]  = fma2(a, dupf(wb.y), acc[5]);
            acc[6]  = fma2(a, dupf(wb.z), acc[6]);
            acc[7]  = fma2(a, dupf(wb.w), acc[7]);
            acc[8]  = fma2(a, dupf(wc.x), acc[8]);
            acc[9]  = fma2(a, dupf(wc.y), acc[9]);
            acc[10] = fma2(a, dupf(wc.z), acc[10]);
            acc[11] = fma2(a, dupf(wc.w), acc[11]);
            acc[12] = fma2(a, dupf(wd.x), acc[12]);
            acc[13] = fma2(a, dupf(wd.y), acc[13]);
            acc[14] = fma2(a, dupf(wd.z), acc[14]);
            acc[15] = fma2(a, dupf(wd.w), acc[15]);
        }
#pragma unroll
        for (int d = 0; d < DM; d++) h[d] = add2(h[d], acc[d]);
        lnorm2(h, S.ln2w[l], S.ln2b[l]);
    }

    // ---- output projection ----
    f2 y2 = dot16(h, S.Wout, dupf(S.bout_));
    if (active) {
        float ya, yb; upk(y2, ya, yb);
        *reinterpret_cast<float2*>(gout + (size_t)t * NSEQ + n0) = make_float2(ya, yb);
    }
}

extern "C" void kernel_launch(void* const* d_in, const int* in_sizes, int n_in,
                              void* d_out, int out_size)
{
    (void)in_sizes; (void)n_in; (void)out_size;
    const float* gx    = (const float*)d_in[0];
    const float* gWin  = (const float*)d_in[1];
    const float* gbin  = (const float*)d_in[2];
    const float* gWqkv = (const float*)d_in[3];
    const float* gbqkv = (const float*)d_in[4];
    const float* gWo   = (const float*)d_in[5];
    const float* gbo   = (const float*)d_in[6];
    const float* gln1w = (const float*)d_in[7];
    const float* gln1b = (const float*)d_in[8];
    const float* gW1   = (const float*)d_in[9];
    const float* gb1   = (const float*)d_in[10];
    const float* gW2   = (const float*)d_in[11];
    const float* gb2   = (const float*)d_in[12];
    const float* gln2w = (const float*)d_in[13];
    const float* gln2b = (const float*)d_in[14];
    const float* gWout = (const float*)d_in[15];
    const float* gbout = (const float*)d_in[16];
    float* gout = (float*)d_out;

    cudaFuncSetAttribute(tt_kernel, cudaFuncAttributeMaxDynamicSharedMemorySize,
                         (int)sizeof(Smem));
    const int npairs = NSEQ / 2;
    tt_kernel<<<npairs / WPC, CTA_THREADS, sizeof(Smem)>>>(
        gx, gWin, gbin, gWqkv, gbqkv, gWo, gbo, gln1w, gln1b,
        gW1, gb1, gW2, gb2, gln2w, gln2b, gWout, gbout, gout);
}